// round 3
// baseline (speedup 1.0000x reference)
#include <cuda_runtime.h>
#include <math.h>

// ---------------- problem constants ----------------
#define Bb    2
#define Ss    2048
#define DIMM  2048
#define NHH   16
#define NKVV  4
#define HDD   128
#define NEE   8
#define HIDD  1024
#define SHIDD 1024
#define TT    4096            // Bb*Ss

// ---------------- scratch (device globals; no allocation allowed) ----------------
__device__ float g_h   [TT * DIMM];          // rmsnorm1 out
__device__ float g_q   [TT * NHH * HDD];     // q (roped in place)
__device__ float g_attn[TT * NHH * HDD];     // attention out
__device__ float g_h2  [TT * DIMM];          // rmsnorm2 out
__device__ float g_t1  [NEE * TT * HIDD];    // expert h1 -> he (in place)
__device__ float g_t3  [NEE * TT * HIDD];    // expert h3
__device__ float g_s1  [TT * SHIDD];         // shared h1 -> hs (in place)
__device__ float g_s3  [TT * SHIDD];         // shared h3
__device__ int   g_cnt [NEE];
__device__ int   g_tok [NEE * TT];
__device__ float g_gt  [NEE * TT];

// ---------------- rmsnorm ----------------
__global__ void rmsnorm_kernel(const float* __restrict__ x, const float* __restrict__ w,
                               float* __restrict__ out)
{
    int t = blockIdx.x;
    const float* xr = x + (size_t)t * DIMM;
    float s = 0.f;
    for (int d = threadIdx.x; d < DIMM; d += 256) { float v = xr[d]; s += v * v; }
    __shared__ float red[256];
    red[threadIdx.x] = s; __syncthreads();
    for (int st = 128; st > 0; st >>= 1) {
        if (threadIdx.x < st) red[threadIdx.x] += red[threadIdx.x + st];
        __syncthreads();
    }
    float rms = rsqrtf(red[0] * (1.f / DIMM) + 1e-6f);
    for (int d = threadIdx.x; d < DIMM; d += 256)
        out[(size_t)t * DIMM + d] = xr[d] * rms * w[d];
}

// ---------------- generic fp32 GEMM: C = A[MxK] @ B[KxN] (+D) ----------------
// All M,N multiples of 128; K multiple of 16 (guaranteed by problem shapes).
#define GBM 128
#define GBN 128
#define GBK 16

__global__ __launch_bounds__(256) void sgemm_kernel(
    const float* __restrict__ A, const float* __restrict__ Bm,
    const float* __restrict__ D, float* __restrict__ C,
    int M, int N, int K)
{
    __shared__ float As[GBK][GBM + 4];
    __shared__ float Bs[GBK][GBN];
    const int tid = threadIdx.x;
    const int tx = tid & 15, ty = tid >> 4;
    const int n0 = blockIdx.x * GBN;
    const int m0 = blockIdx.y * GBM;

    const int a_r = tid >> 2;          // 0..63 (+64)
    const int a_c = (tid & 3) << 2;    // 0,4,8,12
    const int b_k = tid >> 5;          // 0..7 (+8)
    const int b_c = (tid & 31) << 2;   // 0..124

    float acc[8][8];
#pragma unroll
    for (int i = 0; i < 8; i++)
#pragma unroll
        for (int j = 0; j < 8; j++) acc[i][j] = 0.f;

    for (int kt = 0; kt < K; kt += GBK) {
        float4 av0 = *(const float4*)(A + (size_t)(m0 + a_r) * K + kt + a_c);
        float4 av1 = *(const float4*)(A + (size_t)(m0 + a_r + 64) * K + kt + a_c);
        As[a_c + 0][a_r] = av0.x; As[a_c + 1][a_r] = av0.y;
        As[a_c + 2][a_r] = av0.z; As[a_c + 3][a_r] = av0.w;
        As[a_c + 0][a_r + 64] = av1.x; As[a_c + 1][a_r + 64] = av1.y;
        As[a_c + 2][a_r + 64] = av1.z; As[a_c + 3][a_r + 64] = av1.w;
        *(float4*)&Bs[b_k][b_c]     = *(const float4*)(Bm + (size_t)(kt + b_k) * N + n0 + b_c);
        *(float4*)&Bs[b_k + 8][b_c] = *(const float4*)(Bm + (size_t)(kt + b_k + 8) * N + n0 + b_c);
        __syncthreads();
#pragma unroll
        for (int kk = 0; kk < GBK; kk++) {
            float af[8], bf[8];
            *(float4*)&af[0] = *(const float4*)&As[kk][ty << 2];
            *(float4*)&af[4] = *(const float4*)&As[kk][64 + (ty << 2)];
            *(float4*)&bf[0] = *(const float4*)&Bs[kk][tx << 2];
            *(float4*)&bf[4] = *(const float4*)&Bs[kk][64 + (tx << 2)];
#pragma unroll
            for (int i = 0; i < 8; i++)
#pragma unroll
                for (int j = 0; j < 8; j++) acc[i][j] += af[i] * bf[j];
        }
        __syncthreads();
    }
#pragma unroll
    for (int i = 0; i < 8; i++) {
        int r = m0 + ((i < 4) ? (ty * 4 + i) : (64 + ty * 4 + i - 4));
        float* Crow = C + (size_t)r * N + n0;
        float4 r0 = make_float4(acc[i][0], acc[i][1], acc[i][2], acc[i][3]);
        float4 r1 = make_float4(acc[i][4], acc[i][5], acc[i][6], acc[i][7]);
        if (D) {
            const float* Drow = D + (size_t)r * N + n0;
            float4 d0 = *(const float4*)(Drow + tx * 4);
            float4 d1 = *(const float4*)(Drow + 64 + tx * 4);
            r0.x += d0.x; r0.y += d0.y; r0.z += d0.z; r0.w += d0.w;
            r1.x += d1.x; r1.y += d1.y; r1.z += d1.z; r1.w += d1.w;
        }
        *(float4*)(Crow + tx * 4) = r0;
        *(float4*)(Crow + 64 + tx * 4) = r1;
    }
}

// ---------------- RoPE (in place, even/odd interleave) ----------------
__global__ void rope_kernel(float* __restrict__ p, const float* __restrict__ cf,
                            const float* __restrict__ sf, int nheads, int npairs)
{
    int idx = blockIdx.x * 256 + threadIdx.x;
    if (idx >= npairs) return;
    int i = idx & 63;
    int rest = idx >> 6;
    int h = rest % nheads;
    int t = rest / nheads;
    int s = t & (Ss - 1);
    float c = cf[s * 64 + i], sn = sf[s * 64 + i];
    float* q = p + ((size_t)t * nheads + h) * HDD + 2 * i;
    float a = q[0], b = q[1];
    q[0] = a * c - b * sn;
    q[1] = a * sn + b * c;
}

// ---------------- flash causal attention ----------------
#define AQ 64
#define AK 64
#define HDP 132
#define PSP 66
#define ATT_SMEM ((3 * AQ * HDP + AQ * PSP + 3 * AQ) * 4)

__global__ __launch_bounds__(256) void attn_kernel(
    const float* __restrict__ Q, const float* __restrict__ K,
    const float* __restrict__ V, float* __restrict__ O)
{
    extern __shared__ float sm[];
    float* Qs  = sm;
    float* Ks  = Qs + AQ * HDP;
    float* Vs  = Ks + AQ * HDP;
    float* Ps  = Vs + AQ * HDP;
    float* mrow = Ps + AQ * PSP;
    float* lrow = mrow + AQ;
    float* fac  = lrow + AQ;

    const int qt = blockIdx.x, h = blockIdx.y, b = blockIdx.z;
    const int q0 = qt * AQ;
    const int kvh = h >> 2;                 // NH/NKV = 4
    const int tid = threadIdx.x;
    const int tx = tid & 15, ty = tid >> 4;
    const float scale = 0.08838834764831845f;   // 1/sqrt(128)

    const float* Qbase = Q + (((size_t)(b * Ss + q0)) * NHH + h) * HDD;
    for (int idx = tid; idx < AQ * HDD; idx += 256) {
        int r = idx >> 7, d = idx & 127;
        Qs[r * HDP + d] = Qbase[(size_t)r * NHH * HDD + d];
    }
    if (tid < AQ) { mrow[tid] = -1e30f; lrow[tid] = 0.f; }

    float Oa[4][8];
#pragma unroll
    for (int i = 0; i < 4; i++)
#pragma unroll
        for (int j = 0; j < 8; j++) Oa[i][j] = 0.f;

    for (int kt = 0; kt <= qt; kt++) {
        const int k0 = kt * AK;
        __syncthreads();   // protect Ks/Vs against previous phase-B readers
        const float* Kb = K + (((size_t)(b * Ss + k0)) * NKVV + kvh) * HDD;
        const float* Vb = V + (((size_t)(b * Ss + k0)) * NKVV + kvh) * HDD;
        for (int idx = tid; idx < AK * HDD; idx += 256) {
            int r = idx >> 7, d = idx & 127;
            Ks[r * HDP + d] = Kb[(size_t)r * NKVV * HDD + d];
            Vs[r * HDP + d] = Vb[(size_t)r * NKVV * HDD + d];
        }
        __syncthreads();

        // ---- phase A: S = Q K^T (rows ty+16i, cols tx+16j) ----
        float sa[4][4];
#pragma unroll
        for (int i = 0; i < 4; i++)
#pragma unroll
            for (int j = 0; j < 4; j++) sa[i][j] = 0.f;

#pragma unroll 4
        for (int d4 = 0; d4 < HDD; d4 += 4) {
            float4 aF[4], bF[4];
#pragma unroll
            for (int i = 0; i < 4; i++) aF[i] = *(const float4*)&Qs[(ty + 16 * i) * HDP + d4];
#pragma unroll
            for (int j = 0; j < 4; j++) bF[j] = *(const float4*)&Ks[(tx + 16 * j) * HDP + d4];
#pragma unroll
            for (int i = 0; i < 4; i++)
#pragma unroll
                for (int j = 0; j < 4; j++)
                    sa[i][j] += aF[i].x * bF[j].x + aF[i].y * bF[j].y
                              + aF[i].z * bF[j].z + aF[i].w * bF[j].w;
        }
#pragma unroll
        for (int i = 0; i < 4; i++) {
            int r = ty + 16 * i, qg = q0 + r;
#pragma unroll
            for (int j = 0; j < 4; j++) {
                int c = tx + 16 * j;
                float vsc = sa[i][j] * scale;
                if (k0 + c > qg) vsc = -1e30f;
                Ps[r * PSP + c] = vsc;
            }
        }
        __syncthreads();

        // ---- row stats ----
        if (tid < AQ) {
            float mo = mrow[tid], mx = mo;
            for (int c = 0; c < AK; c++) mx = fmaxf(mx, Ps[tid * PSP + c]);
            mrow[tid] = mx;
            fac[tid] = expf(mo - mx);
        }
        __syncthreads();

        // rescale O accumulators + exponentiate P
#pragma unroll
        for (int i = 0; i < 4; i++) {
            float f = fac[ty + 16 * i];
#pragma unroll
            for (int j = 0; j < 8; j++) Oa[i][j] *= f;
        }
        for (int idx = tid; idx < AQ * AK; idx += 256) {
            int r = idx >> 6, c = idx & 63;
            Ps[r * PSP + c] = expf(Ps[r * PSP + c] - mrow[r]);
        }
        __syncthreads();

        if (tid < AQ) {
            float s = 0.f;
            for (int c = 0; c < AK; c++) s += Ps[tid * PSP + c];
            lrow[tid] = lrow[tid] * fac[tid] + s;
        }

        // ---- phase B: O += P V (cols tx*4+j and 64+tx*4+j) ----
#pragma unroll 4
        for (int kk = 0; kk < AK; kk++) {
            float p0 = Ps[(ty)      * PSP + kk];
            float p1 = Ps[(ty + 16) * PSP + kk];
            float p2 = Ps[(ty + 32) * PSP + kk];
            float p3 = Ps[(ty + 48) * PSP + kk];
            float4 v0 = *(const float4*)&Vs[kk * HDP + tx * 4];
            float4 v1 = *(const float4*)&Vs[kk * HDP + 64 + tx * 4];
            Oa[0][0] += p0 * v0.x; Oa[0][1] += p0 * v0.y; Oa[0][2] += p0 * v0.z; Oa[0][3] += p0 * v0.w;
            Oa[0][4] += p0 * v1.x; Oa[0][5] += p0 * v1.y; Oa[0][6] += p0 * v1.z; Oa[0][7] += p0 * v1.w;
            Oa[1][0] += p1 * v0.x; Oa[1][1] += p1 * v0.y; Oa[1][2] += p1 * v0.z; Oa[1][3] += p1 * v0.w;
            Oa[1][4] += p1 * v1.x; Oa[1][5] += p1 * v1.y; Oa[1][6] += p1 * v1.z; Oa[1][7] += p1 * v1.w;
            Oa[2][0] += p2 * v0.x; Oa[2][1] += p2 * v0.y; Oa[2][2] += p2 * v0.z; Oa[2][3] += p2 * v0.w;
            Oa[2][4] += p2 * v1.x; Oa[2][5] += p2 * v1.y; Oa[2][6] += p2 * v1.z; Oa[2][7] += p2 * v1.w;
            Oa[3][0] += p3 * v0.x; Oa[3][1] += p3 * v0.y; Oa[3][2] += p3 * v0.z; Oa[3][3] += p3 * v0.w;
            Oa[3][4] += p3 * v1.x; Oa[3][5] += p3 * v1.y; Oa[3][6] += p3 * v1.z; Oa[3][7] += p3 * v1.w;
        }
    }
    __syncthreads();

    float* Ob = O + (((size_t)(b * Ss + q0)) * NHH + h) * HDD;
#pragma unroll
    for (int i = 0; i < 4; i++) {
        int r = ty + 16 * i;
        float inv = 1.f / lrow[r];
        float4 o0 = make_float4(Oa[i][0] * inv, Oa[i][1] * inv, Oa[i][2] * inv, Oa[i][3] * inv);
        float4 o1 = make_float4(Oa[i][4] * inv, Oa[i][5] * inv, Oa[i][6] * inv, Oa[i][7] * inv);
        *(float4*)(Ob + (size_t)r * NHH * HDD + tx * 4) = o0;
        *(float4*)(Ob + (size_t)r * NHH * HDD + 64 + tx * 4) = o1;
    }
}

// ---------------- MoE routing ----------------
__global__ void zero_cnt_kernel() { if (threadIdx.x < NEE) g_cnt[threadIdx.x] = 0; }

__global__ void route_kernel(const float* __restrict__ h2, const float* __restrict__ gw)
{
    int t = blockIdx.x;
    float part[NEE];
#pragma unroll
    for (int e = 0; e < NEE; e++) part[e] = 0.f;
    for (int d = threadIdx.x; d < DIMM; d += 256) {
        float xv = h2[(size_t)t * DIMM + d];
#pragma unroll
        for (int e = 0; e < NEE; e++) part[e] += xv * gw[d * NEE + e];
    }
    __shared__ float red[256];
    __shared__ float logits[NEE];
    for (int e = 0; e < NEE; e++) {
        red[threadIdx.x] = part[e]; __syncthreads();
        for (int st = 128; st > 0; st >>= 1) {
            if (threadIdx.x < st) red[threadIdx.x] += red[threadIdx.x + st];
            __syncthreads();
        }
        if (threadIdx.x == 0) logits[e] = red[0];
        __syncthreads();
    }
    if (threadIdx.x == 0) {
        int e0 = 0;
        for (int e = 1; e < NEE; e++) if (logits[e] > logits[e0]) e0 = e;
        int e1 = -1;
        for (int e = 0; e < NEE; e++) {
            if (e == e0) continue;
            if (e1 < 0 || logits[e] > logits[e1]) e1 = e;
        }
        float w1e = expf(logits[e1] - logits[e0]);
        float g0 = 1.f / (1.f + w1e);
        float g1 = w1e / (1.f + w1e);
        int p0 = atomicAdd(&g_cnt[e0], 1);
        g_tok[e0 * TT + p0] = t; g_gt[e0 * TT + p0] = g0;
        int p1 = atomicAdd(&g_cnt[e1], 1);
        g_tok[e1 * TT + p1] = t; g_gt[e1 * TT + p1] = g1;
    }
}

// ---------------- gathered expert GEMM: C[slot] = h2[tok[slot]] @ W[e] ----------------
__global__ __launch_bounds__(256) void moe_h_gemm(
    const float* __restrict__ Aglob, const float* __restrict__ W,
    float* __restrict__ Cb, int N, int K)
{
    const int e = blockIdx.z;
    const int cnte = g_cnt[e];
    const int m0 = blockIdx.y * GBM;
    if (m0 >= cnte) return;
    const float* Bm = W + (size_t)e * K * N;

    __shared__ float As[GBK][GBM + 4];
    __shared__ float Bs[GBK][GBN];
    __shared__ int toks[GBM];

    const int tid = threadIdx.x;
    const int tx = tid & 15, ty = tid >> 4;
    const int n0 = blockIdx.x * GBN;
    if (tid < GBM) {
        int r = m0 + tid;
        toks[tid] = (r < cnte) ? g_tok[e * TT + r] : -1;
    }
    __syncthreads();

    const int a_r = tid >> 2;
    const int a_c = (tid & 3) << 2;
    const int b_k = tid >> 5;
    const int b_c = (tid & 31) << 2;
    const int tk0 = toks[a_r], tk1 = toks[a_r + 64];

    float acc[8][8];
#pragma unroll
    for (int i = 0; i < 8; i++)
#pragma unroll
        for (int j = 0; j < 8; j++) acc[i][j] = 0.f;

    for (int kt = 0; kt < K; kt += GBK) {
        float4 av0 = (tk0 >= 0) ? *(const float4*)(Aglob + (size_t)tk0 * K + kt + a_c)
                                : make_float4(0.f, 0.f, 0.f, 0.f);
        float4 av1 = (tk1 >= 0) ? *(const float4*)(Aglob + (size_t)tk1 * K + kt + a_c)
                                : make_float4(0.f, 0.f, 0.f, 0.f);
        As[a_c + 0][a_r] = av0.x; As[a_c + 1][a_r] = av0.y;
        As[a_c + 2][a_r] = av0.z; As[a_c + 3][a_r] = av0.w;
        As[a_c + 0][a_r + 64] = av1.x; As[a_c + 1][a_r + 64] = av1.y;
        As[a_c + 2][a_r + 64] = av1.z; As[a_c + 3][a_r + 64] = av1.w;
        *(float4*)&Bs[b_k][b_c]     = *(const float4*)(Bm + (size_t)(kt + b_k) * N + n0 + b_c);
        *(float4*)&Bs[b_k + 8][b_c] = *(const float4*)(Bm + (size_t)(kt + b_k + 8) * N + n0 + b_c);
        __syncthreads();
#pragma unroll
        for (int kk = 0; kk < GBK; kk++) {
            float af[8], bf[8];
            *(float4*)&af[0] = *(const float4*)&As[kk][ty << 2];
            *(float4*)&af[4] = *(const float4*)&As[kk][64 + (ty << 2)];
            *(float4*)&bf[0] = *(const float4*)&Bs[kk][tx << 2];
            *(float4*)&bf[4] = *(const float4*)&Bs[kk][64 + (tx << 2)];
#pragma unroll
            for (int i = 0; i < 8; i++)
#pragma unroll
                for (int j = 0; j < 8; j++) acc[i][j] += af[i] * bf[j];
        }
        __syncthreads();
    }
#pragma unroll
    for (int i = 0; i < 8; i++) {
        int rl = (i < 4) ? (ty * 4 + i) : (64 + ty * 4 + i - 4);
        if (m0 + rl < cnte) {
            float* Crow = Cb + ((size_t)e * TT + m0 + rl) * N + n0;
            float4 r0 = make_float4(acc[i][0], acc[i][1], acc[i][2], acc[i][3]);
            float4 r1 = make_float4(acc[i][4], acc[i][5], acc[i][6], acc[i][7]);
            *(float4*)(Crow + tx * 4) = r0;
            *(float4*)(Crow + 64 + tx * 4) = r1;
        }
    }
}

// ---------------- expert output GEMM with gated atomic scatter ----------------
__global__ __launch_bounds__(256) void moe_o_gemm(
    const float* __restrict__ He, const float* __restrict__ W2,
    float* __restrict__ outx, int N, int K)
{
    const int e = blockIdx.z;
    const int cnte = g_cnt[e];
    const int m0 = blockIdx.y * GBM;
    if (m0 >= cnte) return;
    const float* A  = He + ((size_t)e * TT + m0) * K;
    const float* Bm = W2 + (size_t)e * K * N;

    __shared__ float As[GBK][GBM + 4];
    __shared__ float Bs[GBK][GBN];
    const int tid = threadIdx.x;
    const int tx = tid & 15, ty = tid >> 4;
    const int n0 = blockIdx.x * GBN;

    const int a_r = tid >> 2;
    const int a_c = (tid & 3) << 2;
    const int b_k = tid >> 5;
    const int b_c = (tid & 31) << 2;

    float acc[8][8];
#pragma unroll
    for (int i = 0; i < 8; i++)
#pragma unroll
        for (int j = 0; j < 8; j++) acc[i][j] = 0.f;

    for (int kt = 0; kt < K; kt += GBK) {
        float4 av0 = *(const float4*)(A + (size_t)a_r * K + kt + a_c);
        float4 av1 = *(const float4*)(A + (size_t)(a_r + 64) * K + kt + a_c);
        As[a_c + 0][a_r] = av0.x; As[a_c + 1][a_r] = av0.y;
        As[a_c + 2][a_r] = av0.z; As[a_c + 3][a_r] = av0.w;
        As[a_c + 0][a_r + 64] = av1.x; As[a_c + 1][a_r + 64] = av1.y;
        As[a_c + 2][a_r + 64] = av1.z; As[a_c + 3][a_r + 64] = av1.w;
        *(float4*)&Bs[b_k][b_c]     = *(const float4*)(Bm + (size_t)(kt + b_k) * N + n0 + b_c);
        *(float4*)&Bs[b_k + 8][b_c] = *(const float4*)(Bm + (size_t)(kt + b_k + 8) * N + n0 + b_c);
        __syncthreads();
#pragma unroll
        for (int kk = 0; kk < GBK; kk++) {
            float af[8], bf[8];
            *(float4*)&af[0] = *(const float4*)&As[kk][ty << 2];
            *(float4*)&af[4] = *(const float4*)&As[kk][64 + (ty << 2)];
            *(float4*)&bf[0] = *(const float4*)&Bs[kk][tx << 2];
            *(float4*)&bf[4] = *(const float4*)&Bs[kk][64 + (tx << 2)];
#pragma unroll
            for (int i = 0; i < 8; i++)
#pragma unroll
                for (int j = 0; j < 8; j++) acc[i][j] += af[i] * bf[j];
        }
        __syncthreads();
    }
#pragma unroll
    for (int i = 0; i < 8; i++) {
        int rl = (i < 4) ? (ty * 4 + i) : (64 + ty * 4 + i - 4);
        int gr = m0 + rl;
        if (gr < cnte) {
            int tk  = g_tok[e * TT + gr];
            float g = g_gt[e * TT + gr];
            float* Orow = outx + (size_t)tk * N + n0;
#pragma unroll
            for (int j = 0; j < 4; j++) atomicAdd(Orow + tx * 4 + j,      g * acc[i][j]);
#pragma unroll
            for (int j = 0; j < 4; j++) atomicAdd(Orow + 64 + tx * 4 + j, g * acc[i][j + 4]);
        }
    }
}

// ---------------- elementwise SwiGLU combine ----------------
__global__ void moe_silu_kernel(float* __restrict__ t1, const float* __restrict__ t3)
{
    size_t idx = (size_t)blockIdx.x * 256 + threadIdx.x;
    if (idx >= (size_t)NEE * TT * HIDD) return;
    int slot = (int)((idx / HIDD) % TT);
    int e = (int)(idx / ((size_t)TT * HIDD));
    if (slot >= g_cnt[e]) return;
    float a = t1[idx];
    t1[idx] = (a / (1.f + expf(-a))) * t3[idx];
}

__global__ void silu_mul_kernel(float* __restrict__ a, const float* __restrict__ b, int n)
{
    int i = blockIdx.x * 256 + threadIdx.x;
    if (i < n) {
        float x = a[i];
        a[i] = (x / (1.f + expf(-x))) * b[i];
    }
}

// ---------------- launch ----------------
extern "C" void kernel_launch(void* const* d_in, const int* in_sizes, int n_in,
                              void* d_out, int out_size)
{
    const float* x   = (const float*)d_in[0];
    const float* fc  = (const float*)d_in[1];
    const float* fs  = (const float*)d_in[2];
    const float* anw = (const float*)d_in[3];
    const float* fnw = (const float*)d_in[4];
    const float* wq  = (const float*)d_in[5];
    const float* wk  = (const float*)d_in[6];
    const float* wv  = (const float*)d_in[7];
    const float* wo  = (const float*)d_in[8];
    const float* gw  = (const float*)d_in[9];
    const float* w1  = (const float*)d_in[10];
    const float* w2  = (const float*)d_in[11];
    const float* w3  = (const float*)d_in[12];
    const float* sw1 = (const float*)d_in[13];
    const float* sw2 = (const float*)d_in[14];
    const float* sw3 = (const float*)d_in[15];

    float* out   = (float*)d_out;
    float* out_x = out;                                      // B*S*DIM
    float* out_k = out + (size_t)TT * DIMM;                  // B*S*NKV*HD (roped)
    float* out_v = out_k + (size_t)TT * NKVV * HDD;          // B*S*NKV*HD (raw)

    float *h, *q, *attn, *h2, *t1, *t3, *s1, *s3;
    cudaGetSymbolAddress((void**)&h,    g_h);
    cudaGetSymbolAddress((void**)&q,    g_q);
    cudaGetSymbolAddress((void**)&attn, g_attn);
    cudaGetSymbolAddress((void**)&h2,   g_h2);
    cudaGetSymbolAddress((void**)&t1,   g_t1);
    cudaGetSymbolAddress((void**)&t3,   g_t3);
    cudaGetSymbolAddress((void**)&s1,   g_s1);
    cudaGetSymbolAddress((void**)&s3,   g_s3);

    cudaFuncSetAttribute(attn_kernel, cudaFuncAttributeMaxDynamicSharedMemorySize, ATT_SMEM);

    // 1) attn rmsnorm
    rmsnorm_kernel<<<TT, 256>>>(x, anw, h);
    // 2) QKV projections
    sgemm_kernel<<<dim3(16, 32), 256>>>(h, wq, nullptr, q,     TT, 2048, 2048);
    sgemm_kernel<<<dim3(4,  32), 256>>>(h, wk, nullptr, out_k, TT, 512,  2048);
    sgemm_kernel<<<dim3(4,  32), 256>>>(h, wv, nullptr, out_v, TT, 512,  2048);
    // 3) RoPE q and k (k in place in output buffer)
    rope_kernel<<<(TT * NHH * 64 + 255) / 256, 256>>>(q,     fc, fs, NHH,  TT * NHH * 64);
    rope_kernel<<<(TT * NKVV * 64 + 255) / 256, 256>>>(out_k, fc, fs, NKVV, TT * NKVV * 64);
    // 4) causal GQA flash attention
    attn_kernel<<<dim3(Ss / AQ, NHH, Bb), 256, ATT_SMEM>>>(q, out_k, out_v, attn);
    // 5) output projection + residual: out_x = attn @ wo + x
    sgemm_kernel<<<dim3(16, 32), 256>>>(attn, wo, x, out_x, TT, 2048, 2048);
    // 6) ffn rmsnorm
    rmsnorm_kernel<<<TT, 256>>>(out_x, fnw, h2);
    // 7) routing (top-2 of 8)
    zero_cnt_kernel<<<1, 32>>>();
    route_kernel<<<TT, 256>>>(h2, gw);
    // 8) routed experts: gathered GEMMs + SwiGLU + scatter-add
    moe_h_gemm<<<dim3(8,  32, NEE), 256>>>(h2, w1, t1, HIDD, DIMM);
    moe_h_gemm<<<dim3(8,  32, NEE), 256>>>(h2, w3, t3, HIDD, DIMM);
    moe_silu_kernel<<<(NEE * TT * HIDD) / 256, 256>>>(t1, t3);
    moe_o_gemm<<<dim3(16, 32, NEE), 256>>>(t1, w2, out_x, DIMM, HIDD);
    // 9) shared expert: out_x += (silu(h2@sw1) * (h2@sw3)) @ sw2
    sgemm_kernel<<<dim3(8, 32), 256>>>(h2, sw1, nullptr, s1, TT, SHIDD, 2048);
    sgemm_kernel<<<dim3(8, 32), 256>>>(h2, sw3, nullptr, s3, TT, SHIDD, 2048);
    silu_mul_kernel<<<(TT * SHIDD) / 256, 256>>>(s1, s3, TT * SHIDD);
    sgemm_kernel<<<dim3(16, 32), 256>>>(s1, sw2, out_x, out_x, TT, 2048, SHIDD);
}